// round 14
// baseline (speedup 1.0000x reference)
#include <cuda_runtime.h>
#include <cstdint>

// S5 SSM scan, B-folded form:
//   x'_t = Atilde * x'_{t-1} + u_t      (input is the FMA addend)
//   y_t  = sum_n (C*Btilde)_n * x'_{t,n}
// batch=32, L=4096, D=256, N=64, fp32.
//
// p=8 mapping: 8 threads per (b,d) channel, 8 states each (4 packed f32x2
// pairs) in registers; reduce via 3x shfl.xor. CTA = 512 threads = 64 channels
// of one batch row; grid = 32 b x 4 d-groups = 128 CTAs -> UNIFORM 1 CTA/SM,
// 4 warps/SMSP (R2-R13 established: uniformity + more warps/SMSP == issue
// efficiency; mixed loading makes under-loaded SMs the stragglers).
// u double-buffered in smem via cp.async (16KB tiles of 64 timesteps).

#define SEQ    4096
#define DMODEL 256
#define DSTATE 64
#define TT     64      // timesteps per smem tile
#define DGC    64      // d-channels per CTA
#define NTH    512     // threads per CTA (16 warps)
#define JH     4       // packed f32x2 pairs per thread (8 states)

typedef unsigned long long u64;

__device__ __forceinline__ u64 pack2(float lo, float hi) {
    u64 r; asm("mov.b64 %0, {%1,%2};" : "=l"(r) : "f"(lo), "f"(hi)); return r;
}
__device__ __forceinline__ float2 unpack2(u64 v) {
    float2 f; asm("mov.b64 {%0,%1}, %2;" : "=f"(f.x), "=f"(f.y) : "l"(v)); return f;
}
__device__ __forceinline__ u64 fma2(u64 a, u64 b, u64 c) {
    u64 d; asm("fma.rn.f32x2 %0, %1, %2, %3;" : "=l"(d) : "l"(a), "l"(b), "l"(c)); return d;
}
__device__ __forceinline__ u64 mul2(u64 a, u64 b) {
    u64 d; asm("mul.rn.f32x2 %0, %1, %2;" : "=l"(d) : "l"(a), "l"(b)); return d;
}
__device__ __forceinline__ u64 add2(u64 a, u64 b) {
    u64 d; asm("add.rn.f32x2 %0, %1, %2;" : "=l"(d) : "l"(a), "l"(b)); return d;
}

__global__ __launch_bounds__(NTH, 1)
void s5_scan_kernel(const float* __restrict__ u,
                    const float* __restrict__ log_dt,
                    const float* __restrict__ A_real,
                    const float* __restrict__ Bm,
                    const float* __restrict__ Cm,
                    const float* __restrict__ x0,
                    float* __restrict__ out)
{
    __shared__ float us[2][TT][DGC];   // 2 x 16KB

    const int tid = threadIdx.x;
    const int c   = tid >> 3;              // channel within CTA (0..63)
    const int h   = tid & 7;               // state octant (8 states each)
    const int b   = blockIdx.x >> 2;       // batch (0..31)
    const int g   = blockIdx.x & 3;        // d-group (0..3)
    const int d0  = g * DGC;
    const int d   = d0 + c;

    // ---- init: discretize + fold Btilde into C ----
    u64 A2[JH], C2[JH], X2[JH];
    {
        const float dt = expf(log_dt[d]);   // DT_SCALE = 1.0
        const int base = d * DSTATE + h * 8;
        #pragma unroll
        for (int j = 0; j < JH; j++) {
            const float ar0 = A_real[base + 2*j];
            const float ar1 = A_real[base + 2*j + 1];
            const float at0 = expf(ar0 * dt);
            const float at1 = expf(ar1 * dt);
            const float bt0 = (1.0f - at0) * Bm[base + 2*j]     / ar0;
            const float bt1 = (1.0f - at1) * Bm[base + 2*j + 1] / ar1;
            A2[j] = pack2(at0, at1);
            C2[j] = pack2(Cm[base + 2*j] * bt0, Cm[base + 2*j + 1] * bt1);
            const float xv0 = x0[base + 2*j];
            const float xv1 = x0[base + 2*j + 1];
            const float xp0 = (bt0 != 0.0f) ? (xv0 / bt0) : 0.0f;
            const float xp1 = (bt1 != 0.0f) ? (xv1 / bt1) : 0.0f;
            X2[j] = pack2(xp0, xp1);
        }
    }

    // ---- u tile prefetch (cp.async, 16B granules; 16KB per tile) ----
    const uint32_t sb0 = (uint32_t)__cvta_generic_to_shared(&us[0][0][0]);
    const uint32_t sb1 = (uint32_t)__cvta_generic_to_shared(&us[1][0][0]);
    const float* gbase = u + ((size_t)b * SEQ) * DMODEL + d0;

    auto load_tile = [&](int t0, int s) {
        const uint32_t sbase = s ? sb1 : sb0;
        #pragma unroll
        for (int k = 0; k < 2; k++) {
            const int idx = tid + k * NTH;           // 0..1023 16B chunks
            const int row = idx >> 4;                // timestep within tile
            const int q   = idx & 15;                // 16B chunk within 256B row
            const float* gp = gbase + (size_t)(t0 + row) * DMODEL + q * 4;
            const uint32_t sa = sbase + (uint32_t)((row * DGC + q * 4) * 4);
            asm volatile("cp.async.cg.shared.global [%0], [%1], 16;" :: "r"(sa), "l"(gp));
        }
        asm volatile("cp.async.commit_group;" ::: "memory");
    };

    const int NT = SEQ / TT;   // 64 tiles
    load_tile(0, 0);

    for (int tile = 0; tile < NT; ++tile) {
        const int cur = tile & 1;
        asm volatile("cp.async.wait_group 0;" ::: "memory");
        __syncthreads();
        if (tile + 1 < NT) load_tile((tile + 1) * TT, cur ^ 1);

        const float* up = &us[cur][0][c];
        float* op = out + (size_t)b * SEQ * DMODEL + (size_t)tile * TT * DMODEL + d;

        #pragma unroll 1
        for (int tt = 0; tt < TT; tt += 4) {
            // prefetch 4 timesteps of u into registers up front
            const float uv0 = up[(tt + 0) * DGC];
            const float uv1 = up[(tt + 1) * DGC];
            const float uv2 = up[(tt + 2) * DGC];
            const float uv3 = up[(tt + 3) * DGC];
            const u64 ubv[4] = { pack2(uv0, uv0), pack2(uv1, uv1),
                                 pack2(uv2, uv2), pack2(uv3, uv3) };

            #pragma unroll
            for (int i = 0; i < 4; ++i) {
                const u64 ub = ubv[i];
                u64 ya, yb;
                X2[0] = fma2(A2[0], X2[0], ub);  ya = mul2(C2[0], X2[0]);
                X2[1] = fma2(A2[1], X2[1], ub);  yb = mul2(C2[1], X2[1]);
                X2[2] = fma2(A2[2], X2[2], ub);  ya = fma2(C2[2], X2[2], ya);
                X2[3] = fma2(A2[3], X2[3], ub);  yb = fma2(C2[3], X2[3], yb);

                const float2 f = unpack2(add2(ya, yb));
                float ys = f.x + f.y;                     // this octant's partial
                ys += __shfl_xor_sync(0xffffffffu, ys, 1);
                ys += __shfl_xor_sync(0xffffffffu, ys, 2);
                ys += __shfl_xor_sync(0xffffffffu, ys, 4);
                if (h == 0) op[(size_t)(tt + i) * DMODEL] = ys;
            }
        }
        __syncthreads();   // protect us[cur] before refill
    }
}

extern "C" void kernel_launch(void* const* d_in, const int* in_sizes, int n_in,
                              void* d_out, int out_size)
{
    const float* u      = (const float*)d_in[0];
    const float* log_dt = (const float*)d_in[1];
    const float* A_real = (const float*)d_in[2];
    const float* B      = (const float*)d_in[3];
    const float* C      = (const float*)d_in[4];
    const float* x0     = (const float*)d_in[5];
    float* out = (float*)d_out;

    s5_scan_kernel<<<128, NTH>>>(u, log_dt, A_real, B, C, x0, out);
}

// round 15
// speedup vs baseline: 2.0895x; 2.0895x over previous
#include <cuda_runtime.h>
#include <cstdint>

// S5 SSM scan, B-folded form:
//   x'_t = Atilde * x'_{t-1} + u_t      (input is the FMA addend)
//   y_t  = sum_n (C*Btilde)_n * x'_{t,n}
// batch=32, L=4096, D=256, N=64, fp32.
//
// Execution shape: EXACTLY R2's (best measured): p=4 threads per (b,d)
// channel, 16 states each (8 packed f32x2 pairs); CTA = 256 threads = 64
// channels; grid = 32 b x 4 d-groups = 128 CTAs -> uniform 1 CTA/SM,
// 2 warps/SMSP. u double-buffered via cp.async.
// NEW vs R2:
//  * lag-1 retired reduction: step t's hadd/shfl/STG tail executes under
//    step t+1's 16 independent FMA2s, so the only inter-step serial
//    dependency is the 4-cyc X update.
//  * 4 y-accumulators (4-deep chains instead of 8-deep).

#define SEQ    4096
#define DMODEL 256
#define DSTATE 64
#define TT     64      // timesteps per smem tile
#define DGC    64      // d-channels per CTA
#define NTH    256     // threads per CTA (8 warps)
#define JH     8       // packed f32x2 pairs per thread (16 states)

typedef unsigned long long u64;

__device__ __forceinline__ u64 pack2(float lo, float hi) {
    u64 r; asm("mov.b64 %0, {%1,%2};" : "=l"(r) : "f"(lo), "f"(hi)); return r;
}
__device__ __forceinline__ float2 unpack2(u64 v) {
    float2 f; asm("mov.b64 {%0,%1}, %2;" : "=f"(f.x), "=f"(f.y) : "l"(v)); return f;
}
__device__ __forceinline__ u64 fma2(u64 a, u64 b, u64 c) {
    u64 d; asm("fma.rn.f32x2 %0, %1, %2, %3;" : "=l"(d) : "l"(a), "l"(b), "l"(c)); return d;
}
__device__ __forceinline__ u64 mul2(u64 a, u64 b) {
    u64 d; asm("mul.rn.f32x2 %0, %1, %2;" : "=l"(d) : "l"(a), "l"(b)); return d;
}
__device__ __forceinline__ u64 add2(u64 a, u64 b) {
    u64 d; asm("add.rn.f32x2 %0, %1, %2;" : "=l"(d) : "l"(a), "l"(b)); return d;
}

__global__ __launch_bounds__(NTH, 1)
void s5_scan_kernel(const float* __restrict__ u,
                    const float* __restrict__ log_dt,
                    const float* __restrict__ A_real,
                    const float* __restrict__ Bm,
                    const float* __restrict__ Cm,
                    const float* __restrict__ x0,
                    float* __restrict__ out)
{
    __shared__ float us[2][TT][DGC];   // 2 x 16KB

    const int tid = threadIdx.x;
    const int c   = tid >> 2;              // channel within CTA (0..63)
    const int h   = tid & 3;               // state quarter (16 states)
    const int b   = blockIdx.x >> 2;       // batch (0..31)
    const int g   = blockIdx.x & 3;        // d-group (0..3)
    const int d0  = g * DGC;
    const int d   = d0 + c;

    // ---- init: discretize + fold Btilde into C ----
    u64 A2[JH], C2[JH], X2[JH];
    {
        const float dt = expf(log_dt[d]);   // DT_SCALE = 1.0
        const int base = d * DSTATE + h * 16;
        #pragma unroll
        for (int j = 0; j < JH; j++) {
            const float ar0 = A_real[base + 2*j];
            const float ar1 = A_real[base + 2*j + 1];
            const float at0 = expf(ar0 * dt);
            const float at1 = expf(ar1 * dt);
            const float bt0 = (1.0f - at0) * Bm[base + 2*j]     / ar0;
            const float bt1 = (1.0f - at1) * Bm[base + 2*j + 1] / ar1;
            A2[j] = pack2(at0, at1);
            C2[j] = pack2(Cm[base + 2*j] * bt0, Cm[base + 2*j + 1] * bt1);
            const float xv0 = x0[base + 2*j];
            const float xv1 = x0[base + 2*j + 1];
            const float xp0 = (bt0 != 0.0f) ? (xv0 / bt0) : 0.0f;
            const float xp1 = (bt1 != 0.0f) ? (xv1 / bt1) : 0.0f;
            X2[j] = pack2(xp0, xp1);
        }
    }

    // ---- u tile prefetch (cp.async, 16B granules; 16KB per tile) ----
    const uint32_t sb0 = (uint32_t)__cvta_generic_to_shared(&us[0][0][0]);
    const uint32_t sb1 = (uint32_t)__cvta_generic_to_shared(&us[1][0][0]);
    const float* gbase = u + ((size_t)b * SEQ) * DMODEL + d0;

    auto load_tile = [&](int t0, int s) {
        const uint32_t sbase = s ? sb1 : sb0;
        #pragma unroll
        for (int k = 0; k < 4; k++) {
            const int idx = tid + k * NTH;           // 0..1023 16B chunks
            const int row = idx >> 4;                // timestep within tile
            const int q   = idx & 15;                // 16B chunk within 256B row
            const float* gp = gbase + (size_t)(t0 + row) * DMODEL + q * 4;
            const uint32_t sa = sbase + (uint32_t)((row * DGC + q * 4) * 4);
            asm volatile("cp.async.cg.shared.global [%0], [%1], 16;" :: "r"(sa), "l"(gp));
        }
        asm volatile("cp.async.commit_group;" ::: "memory");
    };

    const int NT = SEQ / TT;   // 64 tiles
    load_tile(0, 0);

    // lag-1 pipeline state: pending packed partial + its output address.
    // Primed so the first retire writes 0 to the t=0 slot; the genuine t=0
    // tail overwrites it one step later (same thread => ordered).
    u64 pend = pack2(0.0f, 0.0f);
    float* pptr = out + (size_t)b * SEQ * DMODEL + d;

    for (int tile = 0; tile < NT; ++tile) {
        const int cur = tile & 1;
        asm volatile("cp.async.wait_group 0;" ::: "memory");
        __syncthreads();
        if (tile + 1 < NT) load_tile((tile + 1) * TT, cur ^ 1);

        const float* up = &us[cur][0][c];
        float* op = out + (size_t)b * SEQ * DMODEL + (size_t)tile * TT * DMODEL + d;

        #pragma unroll 1
        for (int tt = 0; tt < TT; tt += 4) {
            // prefetch 4 timesteps of u into registers up front
            const float uv0 = up[(tt + 0) * DGC];
            const float uv1 = up[(tt + 1) * DGC];
            const float uv2 = up[(tt + 2) * DGC];
            const float uv3 = up[(tt + 3) * DGC];
            const u64 ubv[4] = { pack2(uv0, uv0), pack2(uv1, uv1),
                                 pack2(uv2, uv2), pack2(uv3, uv3) };

            #pragma unroll
            for (int i = 0; i < 4; ++i) {
                const u64 ub = ubv[i];
                // --- this step's recurrence; 4 independent y chains ---
                u64 ya, yb, yc, yd;
                X2[0] = fma2(A2[0], X2[0], ub);  ya = mul2(C2[0], X2[0]);
                X2[1] = fma2(A2[1], X2[1], ub);  yb = mul2(C2[1], X2[1]);
                X2[2] = fma2(A2[2], X2[2], ub);  yc = mul2(C2[2], X2[2]);
                X2[3] = fma2(A2[3], X2[3], ub);  yd = mul2(C2[3], X2[3]);
                X2[4] = fma2(A2[4], X2[4], ub);  ya = fma2(C2[4], X2[4], ya);
                X2[5] = fma2(A2[5], X2[5], ub);  yb = fma2(C2[5], X2[5], yb);
                X2[6] = fma2(A2[6], X2[6], ub);  yc = fma2(C2[6], X2[6], yc);
                X2[7] = fma2(A2[7], X2[7], ub);  yd = fma2(C2[7], X2[7], yd);
                const u64 np = add2(add2(ya, yb), add2(yc, yd));

                // --- retire PREVIOUS step's tail under this step's FMAs ---
                const float2 f = unpack2(pend);
                float s = f.x + f.y;
                s += __shfl_xor_sync(0xffffffffu, s, 1);
                s += __shfl_xor_sync(0xffffffffu, s, 2);
                if (h == 0) *pptr = s;

                pend = np;
                pptr = op + (size_t)(tt + i) * DMODEL;
            }
        }
        __syncthreads();   // protect us[cur] before refill
    }

    // final flush (tail of the very last step)
    {
        const float2 f = unpack2(pend);
        float s = f.x + f.y;
        s += __shfl_xor_sync(0xffffffffu, s, 1);
        s += __shfl_xor_sync(0xffffffffu, s, 2);
        if (h == 0) *pptr = s;
    }
}

extern "C" void kernel_launch(void* const* d_in, const int* in_sizes, int n_in,
                              void* d_out, int out_size)
{
    const float* u      = (const float*)d_in[0];
    const float* log_dt = (const float*)d_in[1];
    const float* A_real = (const float*)d_in[2];
    const float* B      = (const float*)d_in[3];
    const float* C      = (const float*)d_in[4];
    const float* x0     = (const float*)d_in[5];
    float* out = (float*)d_out;

    s5_scan_kernel<<<128, NTH>>>(u, log_dt, A_real, B, C, x0, out);
}